// round 2
// baseline (speedup 1.0000x reference)
#include <cuda_runtime.h>

// ---------------- problem constants ----------------
#define N_ATOMS     20000
#define N_EDGES     640000
#define N_ANG_EDGES 160000
#define N_PAIRS     560000
#define N_FEAT      407        // 87 onehot + 64 radial + 256 angular

// ---------------- device scratch (allocation-free rule) ----------------
__device__ __align__(16) float g_val   [N_ATOMS * 4];
__device__ __align__(16) float g_edge  [N_ANG_EDGES * 8];   // {d, sw, v0..v3, pad, pad}
__device__ __align__(16) float g_radial[N_ATOMS * 64];
__device__ int   g_count [N_ATOMS];
__device__ int   g_offset[N_ATOMS + 1];
__device__ int   g_cursor[N_ATOMS];
__device__ __align__(16) float g_pay[N_PAIRS * 24];         // {term[16], vp[4], vm[4]}

// ---------------- kernels ----------------

__global__ void k_zero() {
    int idx = blockIdx.x * blockDim.x + threadIdx.x;
    int stride = gridDim.x * blockDim.x;
    float4* r = (float4*)g_radial;
    const float4 z = make_float4(0.f, 0.f, 0.f, 0.f);
    for (int i = idx; i < N_ATOMS * 16; i += stride) r[i] = z;
    for (int i = idx; i < N_ATOMS; i += stride) g_count[i] = 0;
}

// valence gather + angular-edge struct build + pair histogram
__global__ void k_prep(const int* __restrict__ species,
                       const float* __restrict__ vtab,
                       const int* __restrict__ ang_dst,
                       const float* __restrict__ ang_d,
                       const float* __restrict__ ang_sw,
                       const int* __restrict__ catom) {
    int idx = blockIdx.x * blockDim.x + threadIdx.x;
    int stride = gridDim.x * blockDim.x;
    for (int t = idx; t < N_ATOMS; t += stride) {
        int sp = species[t];
        ((float4*)g_val)[t] = *(const float4*)(vtab + sp * 4);
    }
    for (int t = idx; t < N_ANG_EDGES; t += stride) {
        int dst = ang_dst[t];
        int sp  = species[dst];
        float4 v = *(const float4*)(vtab + sp * 4);
        ((float4*)g_edge)[t * 2 + 0] = make_float4(ang_d[t], ang_sw[t], v.x, v.y);
        ((float4*)g_edge)[t * 2 + 1] = make_float4(v.z, v.w, 0.f, 0.f);
    }
    for (int t = idx; t < N_PAIRS; t += stride) {
        atomicAdd(&g_count[catom[t]], 1);
    }
}

// single-block exclusive scan over atom counts
__global__ void k_scan() {
    __shared__ int sdata[1024];
    __shared__ int s_run;
    int t = threadIdx.x;
    if (t == 0) s_run = 0;
    __syncthreads();
    for (int base = 0; base < N_ATOMS; base += 1024) {
        int i = base + t;
        int v = (i < N_ATOMS) ? g_count[i] : 0;
        sdata[t] = v;
        __syncthreads();
        #pragma unroll
        for (int off = 1; off < 1024; off <<= 1) {
            int x = (t >= off) ? sdata[t - off] : 0;
            __syncthreads();
            sdata[t] += x;
            __syncthreads();
        }
        int incl = sdata[t];
        int run = s_run;
        if (i < N_ATOMS) {
            int excl = run + incl - v;
            g_offset[i] = excl;
            g_cursor[i] = excl;
        }
        __syncthreads();
        if (t == 1023) s_run = run + sdata[1023];
        __syncthreads();
    }
    if (t == 0) g_offset[N_ATOMS] = s_run;
}

// thread-per-pair: full math, write payload at sorted position
__global__ void k_scatter(const float* __restrict__ angles,
                          const int* __restrict__ asrc,
                          const int* __restrict__ adst,
                          const int* __restrict__ catom) {
    int p = blockIdx.x * blockDim.x + threadIdx.x;
    if (p >= N_PAIRS) return;

    int ea = asrc[p];
    int eb = adst[p];
    float4 A0 = ((const float4*)g_edge)[ea * 2 + 0];
    float4 A1 = ((const float4*)g_edge)[ea * 2 + 1];
    float4 B0 = ((const float4*)g_edge)[eb * 2 + 0];
    float4 B1 = ((const float4*)g_edge)[eb * 2 + 1];

    float d12 = 0.5f * (A0.x + B0.x);
    float swp = 2.0f * A0.y * B0.y;

    float vp0 = A0.z + B0.z, vp1 = A0.w + B0.w, vp2 = A1.x + B1.x, vp3 = A1.y + B1.y;
    float vm0 = A0.z * B0.z, vm1 = A0.w * B0.w, vm2 = A1.x * B1.x, vm3 = A1.y * B1.y;

    float sn, cs;
    __sincosf(angles[p], &sn, &cs);
    const float CZ[4] = { 0.92387953f,  0.38268343f, -0.38268343f, -0.92387953f};
    const float SZ[4] = { 0.38268343f,  0.92387953f,  0.92387953f,  0.38268343f};
    float f1[4];
    #pragma unroll
    for (int k = 0; k < 4; k++) {
        float u = 0.5f + 0.5f * (cs * CZ[k] + sn * SZ[k]);
        float u2 = u * u, u4 = u2 * u2, u8 = u4 * u4, u16 = u8 * u8;
        f1[k] = u16 * u16;
    }
    float f2[4];
    #pragma unroll
    for (int a = 0; a < 4; a++) {
        float x = d12 - (0.8f + 0.675f * (float)a);
        f2[a] = swp * __expf(-8.0f * x * x);   // fold switch product into term
    }

    int c = catom[p];
    int pos = atomicAdd(&g_cursor[c], 1);
    float4* P = (float4*)(g_pay + pos * 24);
    #pragma unroll
    for (int a = 0; a < 4; a++) {
        P[a] = make_float4(f2[a] * f1[0], f2[a] * f1[1], f2[a] * f1[2], f2[a] * f1[3]);
    }
    P[4] = make_float4(vp0, vp1, vp2, vp3);
    P[5] = make_float4(vm0, vm1, vm2, vm3);
}

// warp-per-atom gather: register accumulation, coalesced store straight to out
__global__ void k_ang_gather(float* __restrict__ out) {
    int gw = (blockIdx.x * blockDim.x + threadIdx.x) >> 5;
    if (gw >= N_ATOMS) return;
    int lane = threadIdx.x & 31;
    int hi = lane >> 4;           // high half of warp -> odd cells
    int i  = (lane & 15) >> 2;    // vp index (fixed per lane)
    int j  = lane & 3;            // vm index (fixed per lane)

    int start = g_offset[gw];
    int end   = g_offset[gw + 1];

    float acc[8];
    #pragma unroll
    for (int r = 0; r < 8; r++) acc[r] = 0.f;

    const float* pay = g_pay;
    for (int p = start; p < end; p++) {
        const float* P = pay + p * 24;
        float wv = P[16 + i] * P[20 + j];
        #pragma unroll
        for (int r = 0; r < 8; r++) {
            acc[r] += wv * P[2 * r + hi];
        }
    }

    float* o = out + (size_t)gw * N_FEAT + 151;
    #pragma unroll
    for (int r = 0; r < 8; r++) o[r * 32 + lane] = acc[r];
}

__global__ void k_radial(const float* __restrict__ dist,
                         const float* __restrict__ sw,
                         const int* __restrict__ src,
                         const int* __restrict__ dst) {
    int e = blockIdx.x * blockDim.x + threadIdx.x;
    if (e >= N_EDGES) return;
    float d = dist[e];
    float s = sw[e];
    int a_src = src[e];
    float4 v = ((const float4*)g_val)[dst[e]];

    const float inv_step = 1.0f / 0.275f;
    float t = (d - 0.8f) * inv_step;
    int j0 = (int)ceilf(t - 3.857f);
    if (j0 < 0) j0 = 0;

    float4* outp = (float4*)(g_radial + a_src * 64);
    #pragma unroll
    for (int jj = 0; jj < 9; jj++) {
        int j = j0 + jj;
        if (j > 15) break;
        float x = d - (0.8f + 0.275f * (float)j);
        float term = 0.25f * s * __expf(-16.0f * x * x);
        if (term > 1e-10f) {
            atomicAdd(outp + j, make_float4(term * v.x, term * v.y,
                                            term * v.z, term * v.w));
        }
    }
}

// onehot + radial columns only (angular written by k_ang_gather)
__global__ void k_final(const int* __restrict__ species,
                        float* __restrict__ out) {
    const int n = N_ATOMS * 151;
    int idx = blockIdx.x * blockDim.x + threadIdx.x;
    int stride = gridDim.x * blockDim.x;
    for (int i = idx; i < n; i += stride) {
        int atom = i / 151;
        int col  = i - atom * 151;
        float v;
        if (col < 87) {
            v = (col == species[atom]) ? 1.0f : 0.0f;
        } else {
            v = g_radial[atom * 64 + (col - 87)];
        }
        out[(size_t)atom * N_FEAT + col] = v;
    }
}

// ---------------- launcher ----------------
extern "C" void kernel_launch(void* const* d_in, const int* in_sizes, int n_in,
                              void* d_out, int out_size) {
    const int*   species = (const int*)  d_in[0];
    const float* dist    = (const float*)d_in[1];
    const float* swch    = (const float*)d_in[2];
    const int*   esrc    = (const int*)  d_in[3];
    const int*   edst    = (const int*)  d_in[4];
    const float* ang     = (const float*)d_in[5];
    const float* adist   = (const float*)d_in[6];
    const float* asw     = (const float*)d_in[7];
    const int*   aedst   = (const int*)  d_in[8];
    const int*   pasrc   = (const int*)  d_in[9];
    const int*   padst   = (const int*)  d_in[10];
    const int*   catom   = (const int*)  d_in[11];
    const float* vtab    = (const float*)d_in[12];
    float* out = (float*)d_out;

    k_zero<<<640, 256>>>();
    k_prep<<<1280, 256>>>(species, vtab, aedst, adist, asw, catom);
    k_scan<<<1, 1024>>>();
    k_scatter<<<(N_PAIRS + 255) / 256, 256>>>(ang, pasrc, padst, catom);
    k_radial<<<(N_EDGES + 255) / 256, 256>>>(dist, swch, esrc, edst);
    k_ang_gather<<<(N_ATOMS * 32 + 255) / 256, 256>>>(out);
    k_final<<<1536, 256>>>(species, out);
}

// round 3
// speedup vs baseline: 1.2298x; 1.2298x over previous
#include <cuda_runtime.h>

// ---------------- problem constants ----------------
#define N_ATOMS     20000
#define N_EDGES     640000
#define N_ANG_EDGES 160000
#define N_PAIRS     560000
#define N_FEAT      407        // 87 onehot + 64 radial + 256 angular

// ---------------- device scratch (allocation-free rule) ----------------
__device__ __align__(16) float g_val   [N_ATOMS * 4];
__device__ __align__(16) float g_edge  [N_ANG_EDGES * 8];   // {d, sw, v0..v3, pad, pad}
__device__ __align__(16) float g_radial[N_ATOMS * 64];
__device__ int   g_count [N_ATOMS];
__device__ int   g_offset[N_ATOMS + 1];
__device__ int   g_cursor[N_ATOMS];
__device__ __align__(16) float g_pay[N_PAIRS * 16];         // {f1[4], f2sw[4], vp[4], vm[4]}

// ---------------- kernels ----------------

__global__ void k_zero() {
    int idx = blockIdx.x * blockDim.x + threadIdx.x;
    int stride = gridDim.x * blockDim.x;
    float4* r = (float4*)g_radial;
    const float4 z = make_float4(0.f, 0.f, 0.f, 0.f);
    for (int i = idx; i < N_ATOMS * 16; i += stride) r[i] = z;
    for (int i = idx; i < N_ATOMS; i += stride) g_count[i] = 0;
}

// valence gather + angular-edge struct build + pair histogram
__global__ void k_prep(const int* __restrict__ species,
                       const float* __restrict__ vtab,
                       const int* __restrict__ ang_dst,
                       const float* __restrict__ ang_d,
                       const float* __restrict__ ang_sw,
                       const int* __restrict__ catom) {
    int idx = blockIdx.x * blockDim.x + threadIdx.x;
    int stride = gridDim.x * blockDim.x;
    for (int t = idx; t < N_ATOMS; t += stride) {
        int sp = species[t];
        ((float4*)g_val)[t] = *(const float4*)(vtab + sp * 4);
    }
    for (int t = idx; t < N_ANG_EDGES; t += stride) {
        int dst = ang_dst[t];
        int sp  = species[dst];
        float4 v = *(const float4*)(vtab + sp * 4);
        ((float4*)g_edge)[t * 2 + 0] = make_float4(ang_d[t], ang_sw[t], v.x, v.y);
        ((float4*)g_edge)[t * 2 + 1] = make_float4(v.z, v.w, 0.f, 0.f);
    }
    for (int t = idx; t < N_PAIRS; t += stride) {
        atomicAdd(&g_count[catom[t]], 1);
    }
}

// single-block exclusive scan: thread-sequential chunks + shuffle block scan
__global__ void k_scan() {
    const int CHUNK = 20;                 // 1024 * 20 = 20480 >= N_ATOMS
    __shared__ int warp_sums[32];
    int t = threadIdx.x;
    int base = t * CHUNK;
    int local[CHUNK];
    int sum = 0;
    #pragma unroll
    for (int u = 0; u < CHUNK; u++) {
        int i = base + u;
        int v = (i < N_ATOMS) ? g_count[i] : 0;
        local[u] = sum;                   // exclusive within chunk
        sum += v;
    }
    int lane = t & 31, wid = t >> 5;
    int incl = sum;
    #pragma unroll
    for (int off = 1; off < 32; off <<= 1) {
        int x = __shfl_up_sync(0xFFFFFFFFu, incl, off);
        if (lane >= off) incl += x;
    }
    if (lane == 31) warp_sums[wid] = incl;
    __syncthreads();
    if (wid == 0) {
        int w = warp_sums[lane];
        #pragma unroll
        for (int off = 1; off < 32; off <<= 1) {
            int x = __shfl_up_sync(0xFFFFFFFFu, w, off);
            if (lane >= off) w += x;
        }
        warp_sums[lane] = w;
    }
    __syncthreads();
    int excl_base = incl - sum + (wid > 0 ? warp_sums[wid - 1] : 0);
    #pragma unroll
    for (int u = 0; u < CHUNK; u++) {
        int i = base + u;
        if (i < N_ATOMS) {
            int e = excl_base + local[u];
            g_offset[i] = e;
            g_cursor[i] = e;
        }
    }
    if (t == 1023) g_offset[N_ATOMS] = excl_base + sum;
}

// thread-per-pair: compute factors, write compact 64B payload at sorted slot
__global__ void k_scatter(const float* __restrict__ angles,
                          const int* __restrict__ asrc,
                          const int* __restrict__ adst,
                          const int* __restrict__ catom) {
    int p = blockIdx.x * blockDim.x + threadIdx.x;
    if (p >= N_PAIRS) return;

    int ea = asrc[p];
    int eb = adst[p];
    float4 A0 = ((const float4*)g_edge)[ea * 2 + 0];
    float4 A1 = ((const float4*)g_edge)[ea * 2 + 1];
    float4 B0 = ((const float4*)g_edge)[eb * 2 + 0];
    float4 B1 = ((const float4*)g_edge)[eb * 2 + 1];

    float d12 = 0.5f * (A0.x + B0.x);
    float swp = 2.0f * A0.y * B0.y;

    float sn, cs;
    __sincosf(angles[p], &sn, &cs);
    const float CZ[4] = { 0.92387953f,  0.38268343f, -0.38268343f, -0.92387953f};
    const float SZ[4] = { 0.38268343f,  0.92387953f,  0.92387953f,  0.38268343f};
    float f1[4];
    #pragma unroll
    for (int k = 0; k < 4; k++) {
        float u = 0.5f + 0.5f * (cs * CZ[k] + sn * SZ[k]);
        float u2 = u * u, u4 = u2 * u2, u8 = u4 * u4, u16 = u8 * u8;
        f1[k] = u16 * u16;
    }
    float f2[4];
    #pragma unroll
    for (int a = 0; a < 4; a++) {
        float x = d12 - (0.8f + 0.675f * (float)a);
        f2[a] = swp * __expf(-8.0f * x * x);
    }

    int c = catom[p];
    int pos = atomicAdd(&g_cursor[c], 1);
    float4* P = (float4*)(g_pay + pos * 16);
    P[0] = make_float4(f1[0], f1[1], f1[2], f1[3]);
    P[1] = make_float4(f2[0], f2[1], f2[2], f2[3]);
    P[2] = make_float4(A0.z + B0.z, A0.w + B0.w, A1.x + B1.x, A1.y + B1.y);
    P[3] = make_float4(A0.z * B0.z, A0.w * B0.w, A1.x * B1.x, A1.y * B1.y);
}

// warp-per-atom gather: register accumulation, coalesced store straight to out
// feature f = (a*4+k)*16 + i*4 + j ; lane covers (hi, i, j), r covers (a, k-pairs):
//   f = r*32 + lane with cell c = 2r+hi = a*4+k  =>  a = r>>1 (static),
//   k = 2*(r&1) + hi  => two hi-selects per pair.
__global__ void k_ang_gather(float* __restrict__ out) {
    int gw = (blockIdx.x * blockDim.x + threadIdx.x) >> 5;
    if (gw >= N_ATOMS) return;
    int lane = threadIdx.x & 31;
    int hi = lane >> 4;
    int i  = (lane & 15) >> 2;
    int j  = lane & 3;

    int start = g_offset[gw];
    int end   = g_offset[gw + 1];

    float acc[8];
    #pragma unroll
    for (int r = 0; r < 8; r++) acc[r] = 0.f;

    for (int p = start; p < end; p++) {
        const float4* P = (const float4*)(g_pay + p * 16);
        float4 F1 = P[0];
        float4 F2 = P[1];
        float vp = ((const float*)(P + 2))[i];
        float vm = ((const float*)(P + 3))[j];
        float wv = vp * vm;
        float f1e = hi ? F1.y : F1.x;       // k = hi      (even r)
        float f1o = hi ? F1.w : F1.z;       // k = 2 + hi  (odd r)
        float we = wv * f1e;
        float wo = wv * f1o;
        acc[0] += we * F2.x;  acc[1] += wo * F2.x;
        acc[2] += we * F2.y;  acc[3] += wo * F2.y;
        acc[4] += we * F2.z;  acc[5] += wo * F2.z;
        acc[6] += we * F2.w;  acc[7] += wo * F2.w;
    }

    float* o = out + (size_t)gw * N_FEAT + 151;
    #pragma unroll
    for (int r = 0; r < 8; r++) o[r * 32 + lane] = acc[r];
}

__global__ void k_radial(const float* __restrict__ dist,
                         const float* __restrict__ sw,
                         const int* __restrict__ src,
                         const int* __restrict__ dst) {
    int e = blockIdx.x * blockDim.x + threadIdx.x;
    if (e >= N_EDGES) return;
    float d = dist[e];
    float s = sw[e];
    int a_src = src[e];
    float4 v = ((const float4*)g_val)[dst[e]];

    const float inv_step = 1.0f / 0.275f;
    float t = (d - 0.8f) * inv_step;
    int j0 = (int)ceilf(t - 3.857f);
    if (j0 < 0) j0 = 0;

    float4* outp = (float4*)(g_radial + a_src * 64);
    #pragma unroll
    for (int jj = 0; jj < 9; jj++) {
        int j = j0 + jj;
        if (j > 15) break;
        float x = d - (0.8f + 0.275f * (float)j);
        float term = 0.25f * s * __expf(-16.0f * x * x);
        if (term > 1e-10f) {
            atomicAdd(outp + j, make_float4(term * v.x, term * v.y,
                                            term * v.z, term * v.w));
        }
    }
}

// onehot + radial columns (angular written by k_ang_gather)
__global__ void k_final(const int* __restrict__ species,
                        float* __restrict__ out) {
    const int n = N_ATOMS * 151;
    int idx = blockIdx.x * blockDim.x + threadIdx.x;
    int stride = gridDim.x * blockDim.x;
    for (int i = idx; i < n; i += stride) {
        int atom = i / 151;
        int col  = i - atom * 151;
        float v;
        if (col < 87) {
            v = (col == species[atom]) ? 1.0f : 0.0f;
        } else {
            v = g_radial[atom * 64 + (col - 87)];
        }
        out[(size_t)atom * N_FEAT + col] = v;
    }
}

// ---------------- launcher ----------------
extern "C" void kernel_launch(void* const* d_in, const int* in_sizes, int n_in,
                              void* d_out, int out_size) {
    const int*   species = (const int*)  d_in[0];
    const float* dist    = (const float*)d_in[1];
    const float* swch    = (const float*)d_in[2];
    const int*   esrc    = (const int*)  d_in[3];
    const int*   edst    = (const int*)  d_in[4];
    const float* ang     = (const float*)d_in[5];
    const float* adist   = (const float*)d_in[6];
    const float* asw     = (const float*)d_in[7];
    const int*   aedst   = (const int*)  d_in[8];
    const int*   pasrc   = (const int*)  d_in[9];
    const int*   padst   = (const int*)  d_in[10];
    const int*   catom   = (const int*)  d_in[11];
    const float* vtab    = (const float*)d_in[12];
    float* out = (float*)d_out;

    k_zero<<<640, 256>>>();
    k_prep<<<1280, 256>>>(species, vtab, aedst, adist, asw, catom);
    k_scan<<<1, 1024>>>();
    k_scatter<<<(N_PAIRS + 255) / 256, 256>>>(ang, pasrc, padst, catom);
    k_radial<<<(N_EDGES + 255) / 256, 256>>>(dist, swch, esrc, edst);
    k_ang_gather<<<(N_ATOMS * 32 + 255) / 256, 256>>>(out);
    k_final<<<1536, 256>>>(species, out);
}